// round 15
// baseline (speedup 1.0000x reference)
#include <cuda_runtime.h>
#include <cstdint>

// Problem constants
#define NXC 64
#define NYC 64
#define SCALE 16
#define PP 15
#define BB 4
#define CC 3
#define HH 1024
#define WW 1024
#define HW (HH*WW)
#define NNODES 4096
#define CHW (CC*HH*WW)
#define NPAIRS_HALF (BB * 63 * 64)      // 16128
#define NPAIRS (2 * NPAIRS_HALF)        // 32256
static const long long A_ELEMS = (long long)BB * NNODES * NNODES;  // 67108864

#define EDGE_BLOCKS 256                  // static: one per (b, y) strip, at t=0
#define TOTAL_BLOCKS 1184                // 148 SMs x 8 blocks = one wave
#define THREADS 256

// Warp-steal fill: 32KB chunks = 2048 float4 = 64 STG.128 per lane.
#define CHUNK_F4 2048
#define CHUNK_ITERS (CHUNK_F4 / 32)      // 64

// Edge scratch (summed over channels): [0,16128) dv, [16128,32256) dh
__device__ float    g_scratch[NPAIRS];
__device__ unsigned g_chunk = 0;         // warp work-stealing counter (reset by scatter)

__global__ void __launch_bounds__(THREADS, 8)
fused_kernel(const float* __restrict__ data,
             float4* __restrict__ out,
             long long a4, unsigned nchunks) {
    const float4* src = (const float4*)data;
    const float4 z = make_float4(0.f, 0.f, 0.f, 0.f);
    int tid = threadIdx.x;
    int lane = tid & 31;

    // ===================== static edge phase (blocks 0..255) =====================
    if (blockIdx.x < EDGE_BLOCKS) {
        int e = blockIdx.x;
        int b = e >> 6;
        int y = e & 63;
        int x = tid >> 2;            // cell column bin
        int q = tid & 3;             // quarter (q==3 masks col 15)
        bool has_v = (y < 63);
        bool has_h = (x < 63);

        const float4* base0 = (const float4*)(data + (long long)b * CHW
                                                    + (long long)(y * SCALE) * WW);
        float sv = 0.f, sh = 0.f;
        #pragma unroll
        for (int c = 0; c < CC; c++) {
            const float4* cb = base0 + (long long)c * (HW / 4);
            #pragma unroll 5
            for (int i = 0; i < PP; i++) {
                const float4* rp = cb + i * (WW / 4);
                float4 a = __ldg(rp + tid);
                if (has_v) {
                    float4 v = __ldg(rp + 4096 + tid);     // +16 rows
                    sv += fabsf(a.x - v.x) + fabsf(a.y - v.y) + fabsf(a.z - v.z);
                    if (q < 3) sv += fabsf(a.w - v.w);
                }
                if (has_h) {
                    float4 hh = __ldg(rp + tid + 4);       // +16 cols
                    sh += fabsf(a.x - hh.x) + fabsf(a.y - hh.y) + fabsf(a.z - hh.z);
                    if (q < 3) sh += fabsf(a.w - hh.w);
                }
            }
        }
        sv += __shfl_xor_sync(0xffffffffu, sv, 1);
        sv += __shfl_xor_sync(0xffffffffu, sv, 2);
        sh += __shfl_xor_sync(0xffffffffu, sh, 1);
        sh += __shfl_xor_sync(0xffffffffu, sh, 2);
        if (q == 0) {
            if (has_v) g_scratch[b * 4032 + y * 64 + x] = sv;
            if (has_h) g_scratch[NPAIRS_HALF + b * 4032 + y * 63 + x] = sh;
        }
        // no fence / no barrier: scatter_kernel is ordered by the kernel boundary;
        // warps fall straight through into the fill pool.
    }

    // ============== warp-granular work-stealing fill / copy (no barriers) ==============
    unsigned w, nxt;
    if (lane == 0) w = atomicAdd(&g_chunk, 1u);
    w = __shfl_sync(0xffffffffu, w, 0);

    while (w < nchunks) {
        if (lane == 0) nxt = atomicAdd(&g_chunk, 1u);   // prefetch next chunk id

        long long base = (long long)w * CHUNK_F4 + lane;
        if (base < a4) {
            // zero chunk (A region; chunks align exactly to the boundary)
            #pragma unroll
            for (int k = 0; k < CHUNK_ITERS; k++)
                __stcs(&out[base + k * 32], z);
        } else {
            // copy chunk (data tail)
            long long s = base - a4;
            #pragma unroll
            for (int k = 0; k < CHUNK_ITERS; k++)
                __stcs(&out[base + k * 32], src[s + k * 32]);
        }

        nxt = __shfl_sync(0xffffffffu, nxt, 0);
        w = nxt;
    }
}

// ---------------------------------------------------------------------------
// Scatter: one thread per STORE (2 per pair). Kernel boundary orders it after
// the fused kernel. Also resets the steal counter for the next graph replay.
// ---------------------------------------------------------------------------
__global__ void scatter_kernel(float* __restrict__ A) {
    int i = blockIdx.x * blockDim.x + threadIdx.x;
    if (i == 0) g_chunk = 0;
    if (i >= 2 * NPAIRS) return;
    int pair = i >> 1;
    int dir  = i & 1;
    float s = g_scratch[pair];
    bool vert = pair < NPAIRS_HALF;
    int idx = vert ? pair : pair - NPAIRS_HALF;
    int b = idx / 4032;
    int rm = idx - b * 4032;
    float* Ab = A + (long long)b * NNODES * NNODES;
    int n0, n1;
    if (vert) {
        int y = rm >> 6, x = rm & 63;
        n0 = y * NXC + x;
        n1 = n0 + NXC;
    } else {
        int y = rm / 63, x = rm - y * 63;
        n0 = y * NXC + x;
        n1 = n0 + 1;
    }
    if (dir) Ab[(long long)n0 * NNODES + n1] = s;
    else     Ab[(long long)n1 * NNODES + n0] = s;
}

extern "C" void kernel_launch(void* const* d_in, const int* in_sizes, int n_in,
                              void* d_out, int out_size) {
    const float* data = (const float*)d_in[0];
    float* out = (float*)d_out;

    long long a_elems = A_ELEMS;
    long long total = (long long)out_size;
    if (total < a_elems) a_elems = total;
    long long a4 = a_elems >> 2;
    long long total4 = total >> 2;
    unsigned nchunks = (unsigned)((total4 + CHUNK_F4 - 1) / CHUNK_F4);

    fused_kernel<<<TOTAL_BLOCKS, THREADS>>>(data, (float4*)out, a4, nchunks);
    scatter_kernel<<<(2 * NPAIRS + THREADS - 1) / THREADS, THREADS>>>(out);
}

// round 16
// speedup vs baseline: 1.3444x; 1.3444x over previous
#include <cuda_runtime.h>
#include <cstdint>

// Problem constants
#define NXC 64
#define NYC 64
#define SCALE 16
#define PP 15
#define BB 4
#define CC 3
#define HH 1024
#define WW 1024
#define HW (HH*WW)
#define NNODES 4096
#define CHW (CC*HH*WW)
#define NPAIRS_HALF (BB * 63 * 64)      // 16128
#define NPAIRS (2 * NPAIRS_HALF)        // 32256
static const long long A_ELEMS = (long long)BB * NNODES * NNODES;  // 67108864

#define EDGE_BLOCKS 256                  // static: one per (b, y) strip, at t=0
#define TOTAL_BLOCKS 1184                // 148 SMs x 8 blocks = one wave
#define THREADS 256

// Block-granular steal, 64KB super-chunks: 4096 float4; warp wid owns an 8KB
// sub-range (512 f4), 16 STG.128 per lane between barriers.
#define CHUNK_F4 4096
#define WARP_F4 512
#define WARP_ITERS (WARP_F4 / 32)        // 16

// Edge scratch (summed over channels): [0,16128) dv, [16128,32256) dh
__device__ float    g_scratch[NPAIRS];
__device__ unsigned g_chunk = 0;         // block work-stealing counter (reset by scatter)

__global__ void __launch_bounds__(THREADS, 8)
fused_kernel(const float* __restrict__ data,
             float4* __restrict__ out,
             long long a4, unsigned nchunks) {
    const float4* src = (const float4*)data;
    const float4 z = make_float4(0.f, 0.f, 0.f, 0.f);
    int tid = threadIdx.x;
    int lane = tid & 31;
    int wid = tid >> 5;

    // ===================== static edge phase (blocks 0..255) =====================
    if (blockIdx.x < EDGE_BLOCKS) {
        int e = blockIdx.x;
        int b = e >> 6;
        int y = e & 63;
        int x = tid >> 2;            // cell column bin
        int q = tid & 3;             // quarter (q==3 masks col 15)
        bool has_v = (y < 63);
        bool has_h = (x < 63);

        const float4* base0 = (const float4*)(data + (long long)b * CHW
                                                    + (long long)(y * SCALE) * WW);
        float sv = 0.f, sh = 0.f;
        #pragma unroll
        for (int c = 0; c < CC; c++) {
            const float4* cb = base0 + (long long)c * (HW / 4);
            #pragma unroll 5
            for (int i = 0; i < PP; i++) {
                const float4* rp = cb + i * (WW / 4);
                float4 a = __ldg(rp + tid);
                if (has_v) {
                    float4 v = __ldg(rp + 4096 + tid);     // +16 rows
                    sv += fabsf(a.x - v.x) + fabsf(a.y - v.y) + fabsf(a.z - v.z);
                    if (q < 3) sv += fabsf(a.w - v.w);
                }
                if (has_h) {
                    float4 hh = __ldg(rp + tid + 4);       // +16 cols
                    sh += fabsf(a.x - hh.x) + fabsf(a.y - hh.y) + fabsf(a.z - hh.z);
                    if (q < 3) sh += fabsf(a.w - hh.w);
                }
            }
        }
        sv += __shfl_xor_sync(0xffffffffu, sv, 1);
        sv += __shfl_xor_sync(0xffffffffu, sv, 2);
        sh += __shfl_xor_sync(0xffffffffu, sh, 1);
        sh += __shfl_xor_sync(0xffffffffu, sh, 2);
        if (q == 0) {
            if (has_v) g_scratch[b * 4032 + y * 64 + x] = sv;
            if (has_h) g_scratch[NPAIRS_HALF + b * 4032 + y * 63 + x] = sh;
        }
        // scatter_kernel is ordered by the kernel boundary — no fence needed.
    }

    // ========== block-granular work-stealing fill / copy (64KB super-chunks) ==========
    __shared__ unsigned s_next;
    if (tid == 0) s_next = atomicAdd(&g_chunk, 1u);
    __syncthreads();
    unsigned w = s_next;

    while (w < nchunks) {
        if (tid == 0) s_next = atomicAdd(&g_chunk, 1u);   // prefetch next chunk id

        long long base = (long long)w * CHUNK_F4 + wid * WARP_F4 + lane;
        if (base < a4) {
            // zero super-chunk (A region; boundary is super-chunk aligned)
            #pragma unroll
            for (int k = 0; k < WARP_ITERS; k++)
                __stcs(&out[base + k * 32], z);
        } else {
            // copy super-chunk (data tail)
            long long s = base - a4;
            #pragma unroll
            for (int k = 0; k < WARP_ITERS; k++)
                __stcs(&out[base + k * 32], src[s + k * 32]);
        }

        __syncthreads();
        w = s_next;
    }
}

// ---------------------------------------------------------------------------
// Scatter: one thread per STORE (2 per pair). Kernel boundary orders it after
// the fused kernel. Also resets the steal counter for the next graph replay.
// ---------------------------------------------------------------------------
__global__ void scatter_kernel(float* __restrict__ A) {
    int i = blockIdx.x * blockDim.x + threadIdx.x;
    if (i == 0) g_chunk = 0;
    if (i >= 2 * NPAIRS) return;
    int pair = i >> 1;
    int dir  = i & 1;
    float s = g_scratch[pair];
    bool vert = pair < NPAIRS_HALF;
    int idx = vert ? pair : pair - NPAIRS_HALF;
    int b = idx / 4032;
    int rm = idx - b * 4032;
    float* Ab = A + (long long)b * NNODES * NNODES;
    int n0, n1;
    if (vert) {
        int y = rm >> 6, x = rm & 63;
        n0 = y * NXC + x;
        n1 = n0 + NXC;
    } else {
        int y = rm / 63, x = rm - y * 63;
        n0 = y * NXC + x;
        n1 = n0 + 1;
    }
    if (dir) Ab[(long long)n0 * NNODES + n1] = s;
    else     Ab[(long long)n1 * NNODES + n0] = s;
}

extern "C" void kernel_launch(void* const* d_in, const int* in_sizes, int n_in,
                              void* d_out, int out_size) {
    const float* data = (const float*)d_in[0];
    float* out = (float*)d_out;

    long long a_elems = A_ELEMS;
    long long total = (long long)out_size;
    if (total < a_elems) a_elems = total;
    long long a4 = a_elems >> 2;
    long long total4 = total >> 2;
    unsigned nchunks = (unsigned)((total4 + CHUNK_F4 - 1) / CHUNK_F4);

    fused_kernel<<<TOTAL_BLOCKS, THREADS>>>(data, (float4*)out, a4, nchunks);
    scatter_kernel<<<(2 * NPAIRS + THREADS - 1) / THREADS, THREADS>>>(out);
}